// round 15
// baseline (speedup 1.0000x reference)
#include <cuda_runtime.h>
#include <math.h>
#include <stdint.h>
#include <cuda_fp16.h>

#define LTOK 2048
#define DMODEL 256
#define NHEADS 8
#define HDIM 32
#define SCALE 0.17677669529663687f  /* 32^-0.5 */
#define LN_EPS 1e-5f
#define SPLIT 8
#define KEYS_PER_SPLIT (LTOK / SPLIT)   /* 256 */
#define NROWS (NHEADS * LTOK)           /* 16384 */

// ---------------- scratch (device globals; no allocation allowed) ----------------
__device__ float    g_Q[LTOK * DMODEL];
__device__ uint32_t g_KhU[NHEADS * LTOK * (HDIM / 2)];  // K f16x2, [head][tok][d/2]
__device__ __half   g_Vth[NHEADS * HDIM * LTOK];        // V f16 transposed [head][d][tok]
__device__ float    g_bias[LTOK * LTOK];
__device__ float    g_att[LTOK * DMODEL];               // merged attention output
__device__ float    g_pacc[SPLIT * NROWS * HDIM];
__device__ float    g_pm[SPLIT * NROWS];
__device__ float    g_pl[SPLIT * NROWS];

// ---------------------------------------------------------------------------------
// helpers
// ---------------------------------------------------------------------------------
__device__ __forceinline__ uint32_t pack_f16(float lo, float hi) {
    uint32_t r;
    asm("cvt.rn.f16x2.f32 %0, %1, %2;" : "=r"(r) : "f"(hi), "f"(lo));
    return r;
}

__device__ __forceinline__ void mma_tf32(float c[4], const uint32_t a[4],
                                         uint32_t b0, uint32_t b1) {
    asm volatile(
        "mma.sync.aligned.m16n8k8.row.col.f32.tf32.tf32.f32 "
        "{%0,%1,%2,%3}, {%4,%5,%6,%7}, {%8,%9}, {%0,%1,%2,%3};\n"
        : "+f"(c[0]), "+f"(c[1]), "+f"(c[2]), "+f"(c[3])
        : "r"(a[0]), "r"(a[1]), "r"(a[2]), "r"(a[3]), "r"(b0), "r"(b1));
}

__device__ __forceinline__ void mma_f16(float c[4], const uint32_t a[4],
                                        uint32_t b0, uint32_t b1) {
    asm volatile(
        "mma.sync.aligned.m16n8k16.row.col.f32.f16.f16.f32 "
        "{%0,%1,%2,%3}, {%4,%5,%6,%7}, {%8,%9}, {%0,%1,%2,%3};\n"
        : "+f"(c[0]), "+f"(c[1]), "+f"(c[2]), "+f"(c[3])
        : "r"(a[0]), "r"(a[1]), "r"(a[2]), "r"(a[3]), "r"(b0), "r"(b1));
}

__device__ __forceinline__ uint32_t smem_u32(const void* p) {
    return (uint32_t)__cvta_generic_to_shared(p);
}
__device__ __forceinline__ void cp_async8(uint32_t dst, const void* src) {
    asm volatile("cp.async.ca.shared.global [%0], [%1], 8;" :: "r"(dst), "l"(src));
}
__device__ __forceinline__ void cp_async16(uint32_t dst, const void* src) {
    asm volatile("cp.async.ca.shared.global [%0], [%1], 16;" :: "r"(dst), "l"(src));
}

// ---------------------------------------------------------------------------------
// QKV GEMM: tile 64(M) x 64(N), 128 threads, raw-bit tf32 staging.
// mode 0 = Q (f32), 1 = K (f16 packed head-blocked), 2 = V (f16 transposed).
// ---------------------------------------------------------------------------------
__global__ void __launch_bounds__(128) gemm_qkv(
    const float* __restrict__ x,
    const float* __restrict__ Wq, const float* __restrict__ bq,
    const float* __restrict__ Wk, const float* __restrict__ bk,
    const float* __restrict__ Wv, const float* __restrict__ bv,
    float* __restrict__ Qo)
{
    __shared__ uint32_t As[64][20];
    __shared__ uint32_t Ws[64][20];
    const int mode = blockIdx.z;
    const float* W; const float* b;
    if (mode == 0)      { W = Wq; b = bq; }
    else if (mode == 1) { W = Wk; b = bk; }
    else                { W = Wv; b = bv; }

    const int tid  = threadIdx.x;
    const int warp = tid >> 5;
    const int lane = tid & 31;
    const int g  = lane >> 2;
    const int tg = lane & 3;
    const int m0 = blockIdx.y * 64, n0 = blockIdx.x * 64;

    float acc[8][4];
    #pragma unroll
    for (int nt = 0; nt < 8; nt++)
        #pragma unroll
        for (int j = 0; j < 4; j++) acc[nt][j] = 0.0f;

    for (int k0 = 0; k0 < DMODEL; k0 += 16) {
        #pragma unroll
        for (int i = tid; i < 256; i += 128) {
            const int r = i >> 2, c4 = (i & 3) << 2;
            *(uint4*)&As[r][c4] = *(const uint4*)(x + (size_t)(m0 + r) * DMODEL + k0 + c4);
            *(uint4*)&Ws[r][c4] = *(const uint4*)(W + (size_t)(n0 + r) * DMODEL + k0 + c4);
        }
        __syncthreads();

        #pragma unroll
        for (int kf = 0; kf < 2; kf++) {
            uint32_t a[4];
            a[0] = As[warp * 16 + g    ][kf * 8 + tg    ];
            a[1] = As[warp * 16 + g + 8][kf * 8 + tg    ];
            a[2] = As[warp * 16 + g    ][kf * 8 + tg + 4];
            a[3] = As[warp * 16 + g + 8][kf * 8 + tg + 4];
            #pragma unroll
            for (int nt = 0; nt < 8; nt++) {
                mma_tf32(acc[nt], a, Ws[nt * 8 + g][kf * 8 + tg],
                                     Ws[nt * 8 + g][kf * 8 + tg + 4]);
            }
        }
        __syncthreads();
    }

    const int mA = m0 + warp * 16 + g;
    const int mB = mA + 8;
    #pragma unroll
    for (int nt = 0; nt < 8; nt++) {
        const int n = n0 + nt * 8 + 2 * tg;
        float2 bb = *(const float2*)(b + n);
        const float v0 = acc[nt][0] + bb.x, v1 = acc[nt][1] + bb.y;
        const float v2 = acc[nt][2] + bb.x, v3 = acc[nt][3] + bb.y;
        if (mode == 0) {
            *(float2*)(Qo + (size_t)mA * DMODEL + n) = make_float2(v0, v1);
            *(float2*)(Qo + (size_t)mB * DMODEL + n) = make_float2(v2, v3);
        } else {
            const int head = n >> 5, dh = n & 31;
            if (mode == 1) {
                g_KhU[((size_t)head * LTOK + mA) * 16 + (dh >> 1)] = pack_f16(v0, v1);
                g_KhU[((size_t)head * LTOK + mB) * 16 + (dh >> 1)] = pack_f16(v2, v3);
            } else {
                __half* vb = g_Vth + (size_t)head * (HDIM * LTOK);
                vb[(dh    ) * LTOK + mA] = __float2half(v0);
                vb[(dh + 1) * LTOK + mA] = __float2half(v1);
                vb[(dh    ) * LTOK + mB] = __float2half(v2);
                vb[(dh + 1) * LTOK + mB] = __float2half(v3);
            }
        }
    }
}

// ---------------------------------------------------------------------------------
// Geometric bias; piecewise-linear tables computed in-block (thread 0).
// ---------------------------------------------------------------------------------
__global__ void __launch_bounds__(256) geo_bias_kernel(
    const float* __restrict__ pts, const float* __restrict__ beta,
    const float* __restrict__ kw1, const float* __restrict__ kb1,
    const float* __restrict__ kw2, const float* __restrict__ kb2)
{
    __shared__ float sp[LTOK * 3];
    __shared__ float sT[32], sS[33], sC[33];
    const int tid = threadIdx.x;

    if (tid == 0) {
        float t[32], ds[32], dc[32];
        int n = 0;
        float S0 = 0.0f, C0 = kb2[0];
        for (int j = 0; j < 32; j++) {
            const float w1 = kw1[j], b1 = kb1[j], w2 = kw2[j];
            if (b1 > 0.0f) { S0 += w1 * w2; C0 += b1 * w2; }
            if (w1 > 0.0f && !(b1 > 0.0f)) {
                t[n] = -b1 / w1; ds[n] = w1 * w2; dc[n] = b1 * w2; n++;
            } else if (w1 < 0.0f && b1 > 0.0f) {
                t[n] = -b1 / w1; ds[n] = -w1 * w2; dc[n] = -b1 * w2; n++;
            }
        }
        for (int i = 1; i < n; i++) {
            float tv = t[i], sv = ds[i], cv = dc[i];
            int j = i - 1;
            while (j >= 0 && t[j] > tv) { t[j+1]=t[j]; ds[j+1]=ds[j]; dc[j+1]=dc[j]; j--; }
            t[j+1] = tv; ds[j+1] = sv; dc[j+1] = cv;
        }
        sS[0] = S0; sC[0] = C0;
        for (int i = 0; i < 32; i++) {
            if (i < n) {
                sT[i] = t[i];
                sS[i+1] = sS[i] + ds[i];
                sC[i+1] = sC[i] + dc[i];
            } else {
                sT[i] = INFINITY;
                sS[i+1] = sS[i];
                sC[i+1] = sC[i];
            }
        }
    }
    for (int i = tid; i < LTOK * 3; i += 256) sp[i] = pts[i];
    __syncthreads();

    const float bet = beta[0];
    const int qbase = blockIdx.x * 4;

    #pragma unroll
    for (int qi = 0; qi < 4; qi++) {
        const int q = qbase + qi;
        const float qx = sp[q*3+0], qy = sp[q*3+1], qz = sp[q*3+2];
        for (int k = tid; k < LTOK; k += 256) {
            const float dx = qx - sp[k*3+0];
            const float dy = qy - sp[k*3+1];
            const float dz = qz - sp[k*3+2];
            const float d = sqrtf(dx*dx + dy*dy + dz*dz);
            int i = 0;
            #pragma unroll
            for (int s = 16; s; s >>= 1) if (sT[i + s - 1] < d) i += s;
            const float b = fmaf(sS[i], d, sC[i]);
            g_bias[q * LTOK + k] = bet * fminf(fmaxf(b, -10.0f), 0.0f);
        }
    }
}

// ---------------------------------------------------------------------------------
// Flash attention, f16 mma both phases, register-direct P, SPLIT-K x8, with
// DOUBLE-BUFFERED cp.async staging. CTA: 128 thr / 4 warps / 128 q; 256 keys.
// Grid = 1024. Smem ~20 KB.
// ---------------------------------------------------------------------------------
__global__ void __launch_bounds__(128) attn_kernel()
{
    __shared__ uint32_t Kt[2][64][20];   // K tile [key][d-pair f16x2]
    __shared__ __half   Vt[2][32][72];   // V tile transposed [d][key]

    const int tid  = threadIdx.x;
    const int warp = tid >> 5;
    const int lane = tid & 31;
    const int g  = lane >> 2;
    const int tg = lane & 3;

    const int split = blockIdx.x & (SPLIT - 1);
    const int qtile = (blockIdx.x >> 3) & 15;
    const int head  = blockIdx.x >> 7;
    const int qw = qtile * 128 + warp * 32;
    const int kbeg = split * KEYS_PER_SPLIT;
    const int kend = kbeg + KEYS_PER_SPLIT;

    const uint32_t* Ksrc = g_KhU + (size_t)head * LTOK * 16;
    const __half*   Vsrc = g_Vth + (size_t)head * (HDIM * LTOK);

    // prologue: async-prefetch tile 0 into buffer 0
    #pragma unroll
    for (int i = tid; i < 512; i += 128) {
        const int r = i >> 3, seg = i & 7;
        cp_async8(smem_u32(&Kt[0][r][seg * 2]),
                  Ksrc + (size_t)(kbeg + r) * 16 + seg * 2);
    }
    #pragma unroll
    for (int i = tid; i < 256; i += 128) {
        const int d = i >> 3, seg = i & 7;
        cp_async16(smem_u32(&Vt[0][d][seg * 8]),
                   Vsrc + (size_t)d * LTOK + kbeg + seg * 8);
    }
    asm volatile("cp.async.commit_group;");

    // Q fragments (f16, pre-scaled)
    uint32_t qfA[2][4], qfB[2][4];
    {
        const float* Qb = g_Q + (size_t)qw * DMODEL + head * HDIM;
        #pragma unroll
        for (int ks = 0; ks < 2; ks++) {
            #pragma unroll
            for (int half = 0; half < 2; half++) {
                const int dof = ks * 16 + half * 8 + 2 * tg;
                float2 q0 = *(const float2*)(Qb + (g     ) * DMODEL + dof);
                float2 q1 = *(const float2*)(Qb + (g +  8) * DMODEL + dof);
                float2 q2 = *(const float2*)(Qb + (g + 16) * DMODEL + dof);
                float2 q3 = *(const float2*)(Qb + (g + 24) * DMODEL + dof);
                qfA[ks][half * 2    ] = pack_f16(SCALE * q0.x, SCALE * q0.y);
                qfA[ks][half * 2 + 1] = pack_f16(SCALE * q1.x, SCALE * q1.y);
                qfB[ks][half * 2    ] = pack_f16(SCALE * q2.x, SCALE * q2.y);
                qfB[ks][half * 2 + 1] = pack_f16(SCALE * q3.x, SCALE * q3.y);
            }
        }
    }

    float oA[4][4], oB[4][4];
    #pragma unroll
    for (int nt = 0; nt < 4; nt++)
        #pragma unroll
        for (int j = 0; j < 4; j++) { oA[nt][j] = 0.0f; oB[nt][j] = 0.0f; }
    float mA0 = -INFINITY, mA1 = -INFINITY, mB0 = -INFINITY, mB1 = -INFINITY;
    float lA0 = 0.0f, lA1 = 0.0f, lB0 = 0.0f, lB1 = 0.0f;

    const float* b0p = g_bias + (size_t)(qw + g) * LTOK + 2 * tg;
    const float* b1p = b0p +  8 * LTOK;
    const float* b2p = b0p + 16 * LTOK;
    const float* b3p = b0p + 24 * LTOK;

    int buf = 0;

    #pragma unroll 1
    for (int t0 = kbeg; t0 < kend; t0 += 64) {
        asm volatile("cp.async.wait_group 0;");
        __syncthreads();

        if (t0 + 64 < kend) {
            const int nb = buf ^ 1;
            #pragma unroll
            for (int i = tid; i < 512; i += 128) {
                const int r = i >> 3, seg = i & 7;
                cp_async8(smem_u32(&Kt[nb][r][seg * 2]),
                          Ksrc + (size_t)(t0 + 64 + r) * 16 + seg * 2);
            }
            #pragma unroll
            for (int i = tid; i < 256; i += 128) {
                const int d = i >> 3, seg = i & 7;
                cp_async16(smem_u32(&Vt[nb][d][seg * 8]),
                           Vsrc + (size_t)d * LTOK + t0 + 64 + seg * 8);
            }
            asm volatile("cp.async.commit_group;");
        }

        // ---- scores (f16 mma) with bias pipelined one nt ahead ----
        float sA[8][4], sB[8][4];
        float2 nb0 = *(const float2*)(b0p + t0);
        float2 nb1 = *(const float2*)(b1p + t0);
        float2 nb2 = *(const float2*)(b2p + t0);
        float2 nb3 = *(const float2*)(b3p + t0);
        #pragma unroll
        for (int nt = 0; nt < 8; nt++) {
            const float2 bb0 = nb0, bb1 = nb1, bb2 = nb2, bb3 = nb3;
            if (nt < 7) {
                nb0 = *(const float2*)(b0p + t0 + (nt + 1) * 8);
                nb1 = *(const float2*)(b1p + t0 + (nt + 1) * 8);
                nb2 = *(const float2*)(b2p + t0 + (nt + 1) * 8);
                nb3 = *(const float2*)(b3p + t0 + (nt + 1) * 8);
            }
            sA[nt][0] = bb0.x; sA[nt][1] = bb0.y;
            sA[nt][2] = bb1.x; sA[nt][3] = bb1.y;
            sB[nt][0] = bb2.x; sB[nt][1] = bb2.y;
            sB[nt][2] = bb3.x; sB[nt][3] = bb3.y;
            #pragma unroll
            for (int ks = 0; ks < 2; ks++) {
                const uint32_t kb0 = Kt[buf][nt * 8 + g][ks * 8 + tg];
                const uint32_t kb1 = Kt[buf][nt * 8 + g][ks * 8 + tg + 4];
                mma_f16(sA[nt], qfA[ks], kb0, kb1);
                mma_f16(sB[nt], qfB[ks], kb0, kb1);
            }
        }

        // ---- online softmax maxes ----
        float x0 = -INFINITY, x1 = -INFINITY, x2 = -INFINITY, x3 = -INFINITY;
        #pragma unroll
        for (int nt = 0; nt < 8; nt++) {
            x0 = fmaxf(x0, fmaxf(sA[nt][0], sA[nt][1]));
            x1 = fmaxf(x1, fmaxf(sA[nt][2], sA[nt][3]));
            x2 = fmaxf(x2, fmaxf(sB[nt][0], sB[nt][1]));
            x3 = fmaxf(x3, fmaxf(sB[nt][2], sB[nt][3]));
        }
        x0 = fmaxf(x0, __shfl_xor_sync(0xffffffffu, x0, 1));
        x0 = fmaxf(x0, __shfl_xor_sync(0xffffffffu, x0, 2));
        x1 = fmaxf(x1, __shfl_xor_sync(0xffffffffu, x1, 1));
        x1 = fmaxf(x1, __shfl_xor_sync(0xffffffffu, x1, 2));
        x2 = fmaxf(x2, __shfl_xor_sync(0xffffffffu, x2, 1));
        x2 = fmaxf(x2, __shfl_xor_sync(0xffffffffu, x2, 2));
        x3 = fmaxf(x3, __shfl_xor_sync(0xffffffffu, x3, 1));
        x3 = fmaxf(x3, __shfl_xor_sync(0xffffffffu, x3, 2));

        const float nA0 = fmaxf(mA0, x0), nA1 = fmaxf(mA1, x1);
        const float nB0 = fmaxf(mB0, x2), nB1 = fmaxf(mB1, x3);
        const float cA0 = __expf(mA0 - nA0), cA1 = __expf(mA1 - nA1);
        const float cB0 = __expf(mB0 - nB0), cB1 = __expf(mB1 - nB1);
        mA0 = nA0; mA1 = nA1; mB0 = nB0; mB1 = nB1;

        #pragma unroll
        for (int nt = 0; nt < 4; nt++) {
            oA[nt][0] *= cA0; oA[nt][1] *= cA0;
            oA[nt][2] *= cA1; oA[nt][3] *= cA1;
            oB[nt][0] *= cB0; oB[nt][1] *= cB0;
            oB[nt][2] *= cB1; oB[nt][3] *= cB1;
        }
        lA0 *= cA0; lA1 *= cA1; lB0 *= cB0; lB1 *= cB1;

        // ---- FUSED exp -> f16 pack -> PV mma, per kc chunk ----
        #pragma unroll
        for (int kc = 0; kc < 4; kc++) {
            const int n0i = 2 * kc, n1i = 2 * kc + 1;
            uint32_t aA[4], aB[4];
            {
                const float pA0 = __expf(sA[n0i][0] - nA0);
                const float pA1 = __expf(sA[n0i][1] - nA0);
                const float pA2 = __expf(sA[n0i][2] - nA1);
                const float pA3 = __expf(sA[n0i][3] - nA1);
                const float pA4 = __expf(sA[n1i][0] - nA0);
                const float pA5 = __expf(sA[n1i][1] - nA0);
                const float pA6 = __expf(sA[n1i][2] - nA1);
                const float pA7 = __expf(sA[n1i][3] - nA1);
                lA0 += pA0 + pA1 + pA4 + pA5;
                lA1 += pA2 + pA3 + pA6 + pA7;
                aA[0] = pack_f16(pA0, pA1);
                aA[1] = pack_f16(pA2, pA3);
                aA[2] = pack_f16(pA4, pA5);
                aA[3] = pack_f16(pA6, pA7);
            }
            {
                const float pB0 = __expf(sB[n0i][0] - nB0);
                const float pB1 = __expf(sB[n0i][1] - nB0);
                const float pB2 = __expf(sB[n0i][2] - nB1);
                const float pB3 = __expf(sB[n0i][3] - nB1);
                const float pB4 = __expf(sB[n1i][0] - nB0);
                const float pB5 = __expf(sB[n1i][1] - nB0);
                const float pB6 = __expf(sB[n1i][2] - nB1);
                const float pB7 = __expf(sB[n1i][3] - nB1);
                lB0 += pB0 + pB1 + pB4 + pB5;
                lB1 += pB2 + pB3 + pB6 + pB7;
                aB[0] = pack_f16(pB0, pB1);
                aB[1] = pack_f16(pB2, pB3);
                aB[2] = pack_f16(pB4, pB5);
                aB[3] = pack_f16(pB6, pB7);
            }
            #pragma unroll
            for (int nt = 0; nt < 4; nt++) {
                const uint32_t vb0 = *(const uint32_t*)&Vt[buf][nt * 8 + g][kc * 16 + 2 * tg];
                const uint32_t vb1 = *(const uint32_t*)&Vt[buf][nt * 8 + g][kc * 16 + 2 * tg + 8];
                mma_f16(oA[nt], aA, vb0, vb1);
                mma_f16(oB[nt], aB, vb0, vb1);
            }
        }
        buf ^= 1;
    }

    // ---- final quad reduction of l ----
    lA0 += __shfl_xor_sync(0xffffffffu, lA0, 1);
    lA0 += __shfl_xor_sync(0xffffffffu, lA0, 2);
    lA1 += __shfl_xor_sync(0xffffffffu, lA1, 1);
    lA1 += __shfl_xor_sync(0xffffffffu, lA1, 2);
    lB0 += __shfl_xor_sync(0xffffffffu, lB0, 1);
    lB0 += __shfl_xor_sync(0xffffffffu, lB0, 2);
    lB1 += __shfl_xor_sync(0xffffffffu, lB1, 1);
    lB1 += __shfl_xor_sync(0xffffffffu, lB1, 2);

    // ---- store unnormalized partials + (m, l) ----
    const int rA0 = head * LTOK + qw + g;
    const int rA1 = rA0 + 8;
    const int rB0 = rA0 + 16;
    const int rB1 = rA0 + 24;
    float* pA0 = g_pacc + ((size_t)split * NROWS + rA0) * HDIM + 2 * tg;
    float* pA1 = g_pacc + ((size_t)split * NROWS + rA1) * HDIM + 2 * tg;
    float* pB0 = g_pacc + ((size_t)split * NROWS + rB0) * HDIM + 2 * tg;
    float* pB1 = g_pacc + ((size_t)split * NROWS + rB1) * HDIM + 2 * tg;
    #pragma unroll
    for (int nt = 0; nt < 4; nt++) {
        *(float2*)(pA0 + nt * 8) = make_float2(oA[nt][0], oA[nt][1]);
        *(float2*)(pA1 + nt * 8) = make_float2(oA[nt][2], oA[nt][3]);
        *(float2*)(pB0 + nt * 8) = make_float2(oB[nt][0], oB[nt][1]);
        *(float2*)(pB1 + nt * 8) = make_float2(oB[nt][2], oB[nt][3]);
    }
    if (tg == 0) {
        g_pm[split * NROWS + rA0] = mA0;  g_pl[split * NROWS + rA0] = lA0;
        g_pm[split * NROWS + rA1] = mA1;  g_pl[split * NROWS + rA1] = lA1;
        g_pm[split * NROWS + rB0] = mB0;  g_pl[split * NROWS + rB0] = lB0;
        g_pm[split * NROWS + rB1] = mB1;  g_pl[split * NROWS + rB1] = lB1;
    }
}

// ---------------------------------------------------------------------------------
// Merge split-K partials (standalone: 512 coalesced blocks, high MLP).
// ---------------------------------------------------------------------------------
__global__ void __launch_bounds__(256) merge_kernel()
{
    const int idx = blockIdx.x * 256 + threadIdx.x;
    const int row = idx >> 3, d4 = idx & 7;

    float mv[SPLIT];
    float mstar = -INFINITY;
    #pragma unroll
    for (int s = 0; s < SPLIT; s++) {
        mv[s] = g_pm[s * NROWS + row];
        mstar = fmaxf(mstar, mv[s]);
    }
    float denom = 0.0f;
    float4 o = make_float4(0.f, 0.f, 0.f, 0.f);
    #pragma unroll
    for (int s = 0; s < SPLIT; s++) {
        const float w = __expf(mv[s] - mstar);
        denom = fmaf(w, g_pl[s * NROWS + row], denom);
        const float4 a = *(const float4*)(g_pacc + ((size_t)s * NROWS + row) * HDIM + d4 * 4);
        o.x = fmaf(w, a.x, o.x);
        o.y = fmaf(w, a.y, o.y);
        o.z = fmaf(w, a.z, o.z);
        o.w = fmaf(w, a.w, o.w);
    }
    const float inv = 1.0f / denom;
    o.x *= inv; o.y *= inv; o.z *= inv; o.w *= inv;

    const int head = row >> 11, q = row & (LTOK - 1);
    *(float4*)(g_att + (size_t)q * DMODEL + head * HDIM + d4 * 4) = o;
}

// ---------------------------------------------------------------------------------
// Fused O-projection + residual + LayerNorm (round-13 version, no merge phase).
// Tile M=16 x N=256, 256 threads, 128 CTAs.
// ---------------------------------------------------------------------------------
__global__ void __launch_bounds__(256) gemm_o_ln(
    const float* __restrict__ A, const float* __restrict__ W,
    const float* __restrict__ bias, const float* __restrict__ resid,
    const float* __restrict__ lng, const float* __restrict__ lnb,
    float* __restrict__ out)
{
    __shared__ uint32_t sbuf[5440];
    uint32_t (*As)[20] = (uint32_t (*)[20])sbuf;         // [16][20]
    uint32_t (*Ws)[20] = (uint32_t (*)[20])(sbuf + 320); // [256][20]
    float (*ybuf)[257] = (float (*)[257])sbuf;           // [16][257]

    const int tid  = threadIdx.x;
    const int warp = tid >> 5;
    const int lane = tid & 31;
    const int g  = lane >> 2;
    const int tg = lane & 3;
    const int wc = warp;
    const int m0 = blockIdx.x * 16;

    float acc[4][4];
    #pragma unroll
    for (int nt = 0; nt < 4; nt++)
        #pragma unroll
        for (int j = 0; j < 4; j++) acc[nt][j] = 0.0f;

    for (int k0 = 0; k0 < DMODEL; k0 += 16) {
        if (tid < 64) {
            const int r = tid >> 2, c4 = (tid & 3) << 2;
            *(uint4*)&As[r][c4] = *(const uint4*)(A + (size_t)(m0 + r) * DMODEL + k0 + c4);
        }
        #pragma unroll
        for (int i = tid; i < 1024; i += 256) {
            const int r = i >> 2, c4 = (i & 3) << 2;
            *(uint4*)&Ws[r][c4] = *(const uint4*)(W + (size_t)r * DMODEL + k0 + c4);
        }
        __syncthreads();

        #pragma unroll
        for (int kf = 0; kf < 2; kf++) {
            uint32_t a[4];
            a[0] = As[g    ][kf * 8 + tg    ];
            a[1] = As[g + 8][kf * 8 + tg    ];
            a[2] = As[g    ][kf * 8 + tg + 4];
            a[3] = As[g + 8][kf * 8 + tg + 4];
            #pragma unroll
            for (int nt = 0; nt < 4; nt++) {
                mma_tf32(acc[nt], a, Ws[wc * 32 + nt * 8 + g][kf * 8 + tg],
                                     Ws[wc * 32 + nt * 8 + g][kf * 8 + tg + 4]);
            }
        }
        __syncthreads();
    }

    #pragma unroll
    for (int nt = 0; nt < 4; nt++) {
        const int n = wc * 32 + nt * 8 + 2 * tg;
        float2 bb = *(const float2*)(bias + n);
        float2 r0 = *(const float2*)(resid + (size_t)(m0 + g    ) * DMODEL + n);
        float2 r1 = *(const float2*)(resid + (size_t)(m0 + g + 8) * DMODEL + n);
        ybuf[g    ][n    ] = acc[nt][0] + bb.x + r0.x;
        ybuf[g    ][n + 1] = acc[nt][1] + bb.y + r0.y;
        ybuf[g + 8][n    ] = acc[nt][2] + bb.x + r1.x;
        ybuf[g + 8][n + 1] = acc[nt][3] + bb.y + r1.y;
    }
    __syncthreads();

    #pragma unroll
    for (int it = 0; it < 2; it++) {
        const int row = warp * 2 + it;
        float vals[8];
        float sum = 0.0f;
        #pragma unroll
        for (int j = 0; j < 8; j++) {
            vals[j] = ybuf[row][lane + 32 * j];
            sum += vals[j];
        }
        #pragma unroll
        for (int o = 16; o; o >>= 1) sum += __shfl_xor_sync(0xffffffffu, sum, o);
        const float mu = sum * (1.0f / 256.0f);
        float sq = 0.0f;
        #pragma unroll
        for (int j = 0; j < 8; j++) {
            const float d = vals[j] - mu;
            sq += d * d;
        }
        #pragma unroll
        for (int o = 16; o; o >>= 1) sq += __shfl_xor_sync(0xffffffffu, sq, o);
        const float rstd = rsqrtf(sq * (1.0f / 256.0f) + LN_EPS);
        #pragma unroll
        for (int j = 0; j < 8; j++) {
            const int col = lane + 32 * j;
            out[(size_t)(m0 + row) * DMODEL + col] =
                (vals[j] - mu) * rstd * lng[col] + lnb[col];
        }
    }
}

// ---------------------------------------------------------------------------------
extern "C" void kernel_launch(void* const* d_in, const int* in_sizes, int n_in,
                              void* d_out, int out_size)
{
    const float* x    = (const float*)d_in[0];
    const float* pts  = (const float*)d_in[1];
    const float* Wq   = (const float*)d_in[2];
    const float* bq   = (const float*)d_in[3];
    const float* Wk   = (const float*)d_in[4];
    const float* bk   = (const float*)d_in[5];
    const float* Wv   = (const float*)d_in[6];
    const float* bv   = (const float*)d_in[7];
    const float* Wo   = (const float*)d_in[8];
    const float* bo   = (const float*)d_in[9];
    const float* beta = (const float*)d_in[10];
    const float* kw1  = (const float*)d_in[11];
    const float* kb1  = (const float*)d_in[12];
    const float* kw2  = (const float*)d_in[13];
    const float* kb2  = (const float*)d_in[14];
    const float* lng  = (const float*)d_in[15];
    const float* lnb  = (const float*)d_in[16];
    float* out = (float*)d_out;

    float *Qb, *Ab;
    cudaGetSymbolAddress((void**)&Qb, g_Q);
    cudaGetSymbolAddress((void**)&Ab, g_att);

    gemm_qkv<<<dim3(DMODEL/64, LTOK/64, 3), 128>>>(x, Wq, bq, Wk, bk, Wv, bv, Qb);

    geo_bias_kernel<<<LTOK / 4, 256>>>(pts, beta, kw1, kb1, kw2, kb2);

    attn_kernel<<<NHEADS * 16 * SPLIT, 128>>>();
    merge_kernel<<<NROWS * 8 / 256, 256>>>();

    gemm_o_ln<<<LTOK / 16, 256>>>(Ab, Wo, bo, x, lng, lnb, out);
}

// round 16
// speedup vs baseline: 1.0251x; 1.0251x over previous
#include <cuda_runtime.h>
#include <math.h>
#include <stdint.h>
#include <cuda_fp16.h>

#define LTOK 2048
#define DMODEL 256
#define NHEADS 8
#define HDIM 32
#define SCALE 0.17677669529663687f  /* 32^-0.5 */
#define LOG2E 1.4426950408889634f
#define LN_EPS 1e-5f
#define SPLIT 8
#define KEYS_PER_SPLIT (LTOK / SPLIT)   /* 256 */
#define NROWS (NHEADS * LTOK)           /* 16384 */

// ---------------- scratch (device globals; no allocation allowed) ----------------
__device__ float    g_Q[LTOK * DMODEL];
__device__ uint32_t g_KhU[NHEADS * LTOK * (HDIM / 2)];  // K f16x2, [head][tok][d/2]
__device__ __half   g_Vth[NHEADS * HDIM * LTOK];        // V f16 transposed [head][d][tok]
__device__ float    g_bias[LTOK * LTOK];                // log2e * beta * clip(bias)
__device__ float    g_att[LTOK * DMODEL];
__device__ float    g_pacc[SPLIT * NROWS * HDIM];
__device__ float    g_pm[SPLIT * NROWS];                // log2-domain maxes
__device__ float    g_pl[SPLIT * NROWS];
__device__ float    g_T[32];
__device__ float    g_S[33];
__device__ float    g_C[33];

// ---------------------------------------------------------------------------------
// helpers
// ---------------------------------------------------------------------------------
__device__ __forceinline__ uint32_t pack_f16(float lo, float hi) {
    uint32_t r;
    asm("cvt.rn.f16x2.f32 %0, %1, %2;" : "=r"(r) : "f"(hi), "f"(lo));
    return r;
}

__device__ __forceinline__ void mma_tf32(float c[4], const uint32_t a[4],
                                         uint32_t b0, uint32_t b1) {
    asm volatile(
        "mma.sync.aligned.m16n8k8.row.col.f32.tf32.tf32.f32 "
        "{%0,%1,%2,%3}, {%4,%5,%6,%7}, {%8,%9}, {%0,%1,%2,%3};\n"
        : "+f"(c[0]), "+f"(c[1]), "+f"(c[2]), "+f"(c[3])
        : "r"(a[0]), "r"(a[1]), "r"(a[2]), "r"(a[3]), "r"(b0), "r"(b1));
}

__device__ __forceinline__ void mma_f16(float c[4], const uint32_t a[4],
                                        uint32_t b0, uint32_t b1) {
    asm volatile(
        "mma.sync.aligned.m16n8k16.row.col.f32.f16.f16.f32 "
        "{%0,%1,%2,%3}, {%4,%5,%6,%7}, {%8,%9}, {%0,%1,%2,%3};\n"
        : "+f"(c[0]), "+f"(c[1]), "+f"(c[2]), "+f"(c[3])
        : "r"(a[0]), "r"(a[1]), "r"(a[2]), "r"(a[3]), "r"(b0), "r"(b1));
}

// ---------------------------------------------------------------------------------
// QKV GEMM: tile 64(M) x 64(N), 128 threads, raw-bit tf32 staging.
// mode 0 = Q (f32), 1 = K (f16 packed head-blocked), 2 = V (f16 transposed).
// ---------------------------------------------------------------------------------
__global__ void __launch_bounds__(128) gemm_qkv(
    const float* __restrict__ x,
    const float* __restrict__ Wq, const float* __restrict__ bq,
    const float* __restrict__ Wk, const float* __restrict__ bk,
    const float* __restrict__ Wv, const float* __restrict__ bv,
    float* __restrict__ Qo)
{
    __shared__ uint32_t As[64][20];
    __shared__ uint32_t Ws[64][20];
    const int mode = blockIdx.z;
    const float* W; const float* b;
    if (mode == 0)      { W = Wq; b = bq; }
    else if (mode == 1) { W = Wk; b = bk; }
    else                { W = Wv; b = bv; }

    const int tid  = threadIdx.x;
    const int warp = tid >> 5;
    const int lane = tid & 31;
    const int g  = lane >> 2;
    const int tg = lane & 3;
    const int m0 = blockIdx.y * 64, n0 = blockIdx.x * 64;

    float acc[8][4];
    #pragma unroll
    for (int nt = 0; nt < 8; nt++)
        #pragma unroll
        for (int j = 0; j < 4; j++) acc[nt][j] = 0.0f;

    for (int k0 = 0; k0 < DMODEL; k0 += 16) {
        #pragma unroll
        for (int i = tid; i < 256; i += 128) {
            const int r = i >> 2, c4 = (i & 3) << 2;
            *(uint4*)&As[r][c4] = *(const uint4*)(x + (size_t)(m0 + r) * DMODEL + k0 + c4);
            *(uint4*)&Ws[r][c4] = *(const uint4*)(W + (size_t)(n0 + r) * DMODEL + k0 + c4);
        }
        __syncthreads();

        #pragma unroll
        for (int kf = 0; kf < 2; kf++) {
            uint32_t a[4];
            a[0] = As[warp * 16 + g    ][kf * 8 + tg    ];
            a[1] = As[warp * 16 + g + 8][kf * 8 + tg    ];
            a[2] = As[warp * 16 + g    ][kf * 8 + tg + 4];
            a[3] = As[warp * 16 + g + 8][kf * 8 + tg + 4];
            #pragma unroll
            for (int nt = 0; nt < 8; nt++) {
                mma_tf32(acc[nt], a, Ws[nt * 8 + g][kf * 8 + tg],
                                     Ws[nt * 8 + g][kf * 8 + tg + 4]);
            }
        }
        __syncthreads();
    }

    const int mA = m0 + warp * 16 + g;
    const int mB = mA + 8;
    #pragma unroll
    for (int nt = 0; nt < 8; nt++) {
        const int n = n0 + nt * 8 + 2 * tg;
        float2 bb = *(const float2*)(b + n);
        const float v0 = acc[nt][0] + bb.x, v1 = acc[nt][1] + bb.y;
        const float v2 = acc[nt][2] + bb.x, v3 = acc[nt][3] + bb.y;
        if (mode == 0) {
            *(float2*)(Qo + (size_t)mA * DMODEL + n) = make_float2(v0, v1);
            *(float2*)(Qo + (size_t)mB * DMODEL + n) = make_float2(v2, v3);
        } else {
            const int head = n >> 5, dh = n & 31;
            if (mode == 1) {
                g_KhU[((size_t)head * LTOK + mA) * 16 + (dh >> 1)] = pack_f16(v0, v1);
                g_KhU[((size_t)head * LTOK + mB) * 16 + (dh >> 1)] = pack_f16(v2, v3);
            } else {
                __half* vb = g_Vth + (size_t)head * (HDIM * LTOK);
                vb[(dh    ) * LTOK + mA] = __float2half(v0);
                vb[(dh + 1) * LTOK + mA] = __float2half(v1);
                vb[(dh    ) * LTOK + mB] = __float2half(v2);
                vb[(dh + 1) * LTOK + mB] = __float2half(v3);
            }
        }
    }
}

// ---------------------------------------------------------------------------------
// Setup: bias MLP piecewise-linear tables. 1 thread.
// ---------------------------------------------------------------------------------
__global__ void setup_geo_tables(
    const float* __restrict__ kw1, const float* __restrict__ kb1,
    const float* __restrict__ kw2, const float* __restrict__ kb2)
{
    float t[32], ds[32], dc[32];
    int n = 0;
    float S0 = 0.0f, C0 = kb2[0];
    for (int j = 0; j < 32; j++) {
        const float w1 = kw1[j], b1 = kb1[j], w2 = kw2[j];
        if (b1 > 0.0f) { S0 += w1 * w2; C0 += b1 * w2; }
        if (w1 > 0.0f && !(b1 > 0.0f)) {
            t[n] = -b1 / w1; ds[n] = w1 * w2; dc[n] = b1 * w2; n++;
        } else if (w1 < 0.0f && b1 > 0.0f) {
            t[n] = -b1 / w1; ds[n] = -w1 * w2; dc[n] = -b1 * w2; n++;
        }
    }
    for (int i = 1; i < n; i++) {
        float tv = t[i], sv = ds[i], cv = dc[i];
        int j = i - 1;
        while (j >= 0 && t[j] > tv) { t[j+1]=t[j]; ds[j+1]=ds[j]; dc[j+1]=dc[j]; j--; }
        t[j+1] = tv; ds[j+1] = sv; dc[j+1] = cv;
    }
    g_S[0] = S0; g_C[0] = C0;
    for (int i = 0; i < 32; i++) {
        if (i < n) {
            g_T[i] = t[i];
            g_S[i+1] = g_S[i] + ds[i];
            g_C[i+1] = g_C[i] + dc[i];
        } else {
            g_T[i] = INFINITY;
            g_S[i+1] = g_S[i];
            g_C[i+1] = g_C[i];
        }
    }
}

// ---------------------------------------------------------------------------------
// Geometric bias via table lookup. Output pre-scaled by beta*LOG2E (log2 domain).
// ---------------------------------------------------------------------------------
__global__ void __launch_bounds__(256) geo_bias_kernel(
    const float* __restrict__ pts, const float* __restrict__ beta)
{
    __shared__ float sp[LTOK * 3];
    __shared__ float sT[32], sS[33], sC[33];
    const int tid = threadIdx.x;
    for (int i = tid; i < LTOK * 3; i += 256) sp[i] = pts[i];
    if (tid < 32) sT[tid] = g_T[tid];
    if (tid < 33) { sS[tid] = g_S[tid]; sC[tid] = g_C[tid]; }
    __syncthreads();

    const float bet = beta[0] * LOG2E;
    const int qbase = blockIdx.x * 4;

    #pragma unroll
    for (int qi = 0; qi < 4; qi++) {
        const int q = qbase + qi;
        const float qx = sp[q*3+0], qy = sp[q*3+1], qz = sp[q*3+2];
        for (int k = tid; k < LTOK; k += 256) {
            const float dx = qx - sp[k*3+0];
            const float dy = qy - sp[k*3+1];
            const float dz = qz - sp[k*3+2];
            const float d = sqrtf(dx*dx + dy*dy + dz*dz);
            int i = 0;
            #pragma unroll
            for (int s = 16; s; s >>= 1) if (sT[i + s - 1] < d) i += s;
            const float b = fmaf(sS[i], d, sC[i]);
            g_bias[q * LTOK + k] = bet * fminf(fmaxf(b, -10.0f), 0.0f);
        }
    }
}

// ---------------------------------------------------------------------------------
// Flash attention, f16 mma both phases, register-direct P, SPLIT-K x8.
// LOG2-DOMAIN softmax: Q scaled by SCALE*LOG2E, bias pre-scaled by LOG2E,
// all exponentials are bare exp2f (pure MUFU, no FMUL).
// K/V arrive pre-converted f16 (from gemm_qkv); staging is pure vector copy.
// CTA: 128 threads / 4 warps / 128 queries; 256 keys per CTA. Grid = 1024.
// ---------------------------------------------------------------------------------
__global__ void __launch_bounds__(128) attn_kernel()
{
    __shared__ uint32_t Kt[64][20];   // K tile [key][d-pair f16x2]
    __shared__ __half   Vt[32][72];   // V tile transposed [d][key], f16

    const int tid  = threadIdx.x;
    const int warp = tid >> 5;
    const int lane = tid & 31;
    const int g  = lane >> 2;
    const int tg = lane & 3;

    const int split = blockIdx.x & (SPLIT - 1);
    const int qtile = (blockIdx.x >> 3) & 15;
    const int head  = blockIdx.x >> 7;
    const int qw = qtile * 128 + warp * 32;
    const int kbeg = split * KEYS_PER_SPLIT;

    const uint32_t* Ksrc = g_KhU + (size_t)head * LTOK * 16;
    const __half*   Vsrc = g_Vth + (size_t)head * (HDIM * LTOK);

    // Q fragments (f16, pre-scaled by SCALE*LOG2E)
    const float QS = SCALE * LOG2E;
    uint32_t qfA[2][4], qfB[2][4];
    {
        const float* Qb = g_Q + (size_t)qw * DMODEL + head * HDIM;
        #pragma unroll
        for (int ks = 0; ks < 2; ks++) {
            #pragma unroll
            for (int half = 0; half < 2; half++) {
                const int dof = ks * 16 + half * 8 + 2 * tg;
                float2 q0 = *(const float2*)(Qb + (g     ) * DMODEL + dof);
                float2 q1 = *(const float2*)(Qb + (g +  8) * DMODEL + dof);
                float2 q2 = *(const float2*)(Qb + (g + 16) * DMODEL + dof);
                float2 q3 = *(const float2*)(Qb + (g + 24) * DMODEL + dof);
                qfA[ks][half * 2    ] = pack_f16(QS * q0.x, QS * q0.y);
                qfA[ks][half * 2 + 1] = pack_f16(QS * q1.x, QS * q1.y);
                qfB[ks][half * 2    ] = pack_f16(QS * q2.x, QS * q2.y);
                qfB[ks][half * 2 + 1] = pack_f16(QS * q3.x, QS * q3.y);
            }
        }
    }

    float oA[4][4], oB[4][4];
    #pragma unroll
    for (int nt = 0; nt < 4; nt++)
        #pragma unroll
        for (int j = 0; j < 4; j++) { oA[nt][j] = 0.0f; oB[nt][j] = 0.0f; }
    float mA0 = -INFINITY, mA1 = -INFINITY, mB0 = -INFINITY, mB1 = -INFINITY;
    float lA0 = 0.0f, lA1 = 0.0f, lB0 = 0.0f, lB1 = 0.0f;

    const float* b0p = g_bias + (size_t)(qw + g) * LTOK + 2 * tg;
    const float* b1p = b0p +  8 * LTOK;
    const float* b2p = b0p + 16 * LTOK;
    const float* b3p = b0p + 24 * LTOK;

    #pragma unroll 1
    for (int t0 = kbeg; t0 < kbeg + KEYS_PER_SPLIT; t0 += 64) {
        // ---- stage K/V: pure vector copies (pre-converted f16 layouts) ----
        #pragma unroll
        for (int i = tid; i < 512; i += 128) {
            const int r = i >> 3, seg = i & 7;
            *(uint2*)&Kt[r][seg * 2] =
                *(const uint2*)(Ksrc + (size_t)(t0 + r) * 16 + seg * 2);
        }
        #pragma unroll
        for (int i = tid; i < 256; i += 128) {
            const int d = i >> 3, seg = i & 7;
            *(uint4*)&Vt[d][seg * 8] =
                *(const uint4*)(Vsrc + (size_t)d * LTOK + t0 + seg * 8);
        }
        __syncthreads();

        // ---- scores (f16 mma) with bias pipelined one nt ahead ----
        float sA[8][4], sB[8][4];
        float2 nb0 = *(const float2*)(b0p + t0);
        float2 nb1 = *(const float2*)(b1p + t0);
        float2 nb2 = *(const float2*)(b2p + t0);
        float2 nb3 = *(const float2*)(b3p + t0);
        #pragma unroll
        for (int nt = 0; nt < 8; nt++) {
            const float2 bb0 = nb0, bb1 = nb1, bb2 = nb2, bb3 = nb3;
            if (nt < 7) {
                nb0 = *(const float2*)(b0p + t0 + (nt + 1) * 8);
                nb1 = *(const float2*)(b1p + t0 + (nt + 1) * 8);
                nb2 = *(const float2*)(b2p + t0 + (nt + 1) * 8);
                nb3 = *(const float2*)(b3p + t0 + (nt + 1) * 8);
            }
            sA[nt][0] = bb0.x; sA[nt][1] = bb0.y;
            sA[nt][2] = bb1.x; sA[nt][3] = bb1.y;
            sB[nt][0] = bb2.x; sB[nt][1] = bb2.y;
            sB[nt][2] = bb3.x; sB[nt][3] = bb3.y;
            #pragma unroll
            for (int ks = 0; ks < 2; ks++) {
                const uint32_t kb0 = Kt[nt * 8 + g][ks * 8 + tg];
                const uint32_t kb1 = Kt[nt * 8 + g][ks * 8 + tg + 4];
                mma_f16(sA[nt], qfA[ks], kb0, kb1);
                mma_f16(sB[nt], qfB[ks], kb0, kb1);
            }
        }

        // ---- online softmax maxes (log2 domain) ----
        float x0 = -INFINITY, x1 = -INFINITY, x2 = -INFINITY, x3 = -INFINITY;
        #pragma unroll
        for (int nt = 0; nt < 8; nt++) {
            x0 = fmaxf(x0, fmaxf(sA[nt][0], sA[nt][1]));
            x1 = fmaxf(x1, fmaxf(sA[nt][2], sA[nt][3]));
            x2 = fmaxf(x2, fmaxf(sB[nt][0], sB[nt][1]));
            x3 = fmaxf(x3, fmaxf(sB[nt][2], sB[nt][3]));
        }
        x0 = fmaxf(x0, __shfl_xor_sync(0xffffffffu, x0, 1));
        x0 = fmaxf(x0, __shfl_xor_sync(0xffffffffu, x0, 2));
        x1 = fmaxf(x1, __shfl_xor_sync(0xffffffffu, x1, 1));
        x1 = fmaxf(x1, __shfl_xor_sync(0xffffffffu, x1, 2));
        x2 = fmaxf(x2, __shfl_xor_sync(0xffffffffu, x2, 1));
        x2 = fmaxf(x2, __shfl_xor_sync(0xffffffffu, x2, 2));
        x3 = fmaxf(x3, __shfl_xor_sync(0xffffffffu, x3, 1));
        x3 = fmaxf(x3, __shfl_xor_sync(0xffffffffu, x3, 2));

        const float nA0 = fmaxf(mA0, x0), nA1 = fmaxf(mA1, x1);
        const float nB0 = fmaxf(mB0, x2), nB1 = fmaxf(mB1, x3);
        const float cA0 = exp2f(mA0 - nA0), cA1 = exp2f(mA1 - nA1);
        const float cB0 = exp2f(mB0 - nB0), cB1 = exp2f(mB1 - nB1);
        mA0 = nA0; mA1 = nA1; mB0 = nB0; mB1 = nB1;

        #pragma unroll
        for (int nt = 0; nt < 4; nt++) {
            oA[nt][0] *= cA0; oA[nt][1] *= cA0;
            oA[nt][2] *= cA1; oA[nt][3] *= cA1;
            oB[nt][0] *= cB0; oB[nt][1] *= cB0;
            oB[nt][2] *= cB1; oB[nt][3] *= cB1;
        }
        lA0 *= cA0; lA1 *= cA1; lB0 *= cB0; lB1 *= cB1;

        // ---- FUSED exp2 -> f16 pack -> PV mma, per kc chunk ----
        #pragma unroll
        for (int kc = 0; kc < 4; kc++) {
            const int n0i = 2 * kc, n1i = 2 * kc + 1;
            uint32_t aA[4], aB[4];
            {
                const float pA0 = exp2f(sA[n0i][0] - nA0);
                const float pA1 = exp2f(sA[n0i][1] - nA0);
                const float pA2 = exp2f(sA[n0i][2] - nA1);
                const float pA3 = exp2f(sA[n0i][3] - nA1);
                const float pA4 = exp2f(sA[n1i][0] - nA0);
                const float pA5 = exp2f(sA[n1i][1] - nA0);
                const float pA6 = exp2f(sA[n1i][2] - nA1);
                const float pA7 = exp2f(sA[n1i][3] - nA1);
                lA0 += pA0 + pA1 + pA4 + pA5;
                lA1 += pA2 + pA3 + pA6 + pA7;
                aA[0] = pack_f16(pA0, pA1);
                aA[1] = pack_f16(pA2, pA3);
                aA[2] = pack_f16(pA4, pA5);
                aA[3] = pack_f16(pA6, pA7);
            }
            {
                const float pB0 = exp2f(sB[n0i][0] - nB0);
                const float pB1 = exp2f(sB[n0i][1] - nB0);
                const float pB2 = exp2f(sB[n0i][2] - nB1);
                const float pB3 = exp2f(sB[n0i][3] - nB1);
                const float pB4 = exp2f(sB[n1i][0] - nB0);
                const float pB5 = exp2f(sB[n1i][1] - nB0);
                const float pB6 = exp2f(sB[n1i][2] - nB1);
                const float pB7 = exp2f(sB[n1i][3] - nB1);
                lB0 += pB0 + pB1 + pB4 + pB5;
                lB1 += pB2 + pB3 + pB6 + pB7;
                aB[0] = pack_f16(pB0, pB1);
                aB[1] = pack_f16(pB2, pB3);
                aB[2] = pack_f16(pB4, pB5);
                aB[3] = pack_f16(pB6, pB7);
            }
            #pragma unroll
            for (int nt = 0; nt < 4; nt++) {
                const uint32_t vb0 = *(const uint32_t*)&Vt[nt * 8 + g][kc * 16 + 2 * tg];
                const uint32_t vb1 = *(const uint32_t*)&Vt[nt * 8 + g][kc * 16 + 2 * tg + 8];
                mma_f16(oA[nt], aA, vb0, vb1);
                mma_f16(oB[nt], aB, vb0, vb1);
            }
        }
        __syncthreads();
    }

    // ---- final quad reduction of l ----
    lA0 += __shfl_xor_sync(0xffffffffu, lA0, 1);
    lA0 += __shfl_xor_sync(0xffffffffu, lA0, 2);
    lA1 += __shfl_xor_sync(0xffffffffu, lA1, 1);
    lA1 += __shfl_xor_sync(0xffffffffu, lA1, 2);
    lB0 += __shfl_xor_sync(0xffffffffu, lB0, 1);
    lB0 += __shfl_xor_sync(0xffffffffu, lB0, 2);
    lB1 += __shfl_xor_sync(0xffffffffu, lB1, 1);
    lB1 += __shfl_xor_sync(0xffffffffu, lB1, 2);

    // ---- store unnormalized partials + (m, l) ----
    const int rA0 = head * LTOK + qw + g;
    const int rA1 = rA0 + 8;
    const int rB0 = rA0 + 16;
    const int rB1 = rA0 + 24;
    float* pA0 = g_pacc + ((size_t)split * NROWS + rA0) * HDIM + 2 * tg;
    float* pA1 = g_pacc + ((size_t)split * NROWS + rA1) * HDIM + 2 * tg;
    float* pB0 = g_pacc + ((size_t)split * NROWS + rB0) * HDIM + 2 * tg;
    float* pB1 = g_pacc + ((size_t)split * NROWS + rB1) * HDIM + 2 * tg;
    #pragma unroll
    for (int nt = 0; nt < 4; nt++) {
        *(float2*)(pA0 + nt * 8) = make_float2(oA[nt][0], oA[nt][1]);
        *(float2*)(pA1 + nt * 8) = make_float2(oA[nt][2], oA[nt][3]);
        *(float2*)(pB0 + nt * 8) = make_float2(oB[nt][0], oB[nt][1]);
        *(float2*)(pB1 + nt * 8) = make_float2(oB[nt][2], oB[nt][3]);
    }
    if (tg == 0) {
        g_pm[split * NROWS + rA0] = mA0;  g_pl[split * NROWS + rA0] = lA0;
        g_pm[split * NROWS + rA1] = mA1;  g_pl[split * NROWS + rA1] = lA1;
        g_pm[split * NROWS + rB0] = mB0;  g_pl[split * NROWS + rB0] = lB0;
        g_pm[split * NROWS + rB1] = mB1;  g_pl[split * NROWS + rB1] = lB1;
    }
}

// ---------------------------------------------------------------------------------
// Merge split-K partials: 2 rows per thread, split loops interleaved (MLP 16).
// 256 blocks x 256 threads. m's are log2-domain -> exp2f.
// ---------------------------------------------------------------------------------
__global__ void __launch_bounds__(256) merge_kernel()
{
    const int idx  = blockIdx.x * 256 + threadIdx.x;     // 65536 threads
    const int rowA = idx >> 3;                            // 0..8191
    const int rowB = rowA + (NROWS / 2);                  // 8192..16383
    const int d4   = idx & 7;

    float mvA[SPLIT], mvB[SPLIT];
    float msA = -INFINITY, msB = -INFINITY;
    #pragma unroll
    for (int s = 0; s < SPLIT; s++) {
        mvA[s] = g_pm[s * NROWS + rowA];
        mvB[s] = g_pm[s * NROWS + rowB];
        msA = fmaxf(msA, mvA[s]);
        msB = fmaxf(msB, mvB[s]);
    }
    float wA[SPLIT], wB[SPLIT];
    float denA = 0.0f, denB = 0.0f;
    #pragma unroll
    for (int s = 0; s < SPLIT; s++) {
        wA[s] = exp2f(mvA[s] - msA);
        wB[s] = exp2f(mvB[s] - msB);
        denA = fmaf(wA[s], g_pl[s * NROWS + rowA], denA);
        denB = fmaf(wB[s], g_pl[s * NROWS + rowB], denB);
    }

    float4 oA = make_float4(0.f, 0.f, 0.f, 0.f);
    float4 oB = make_float4(0.f, 0.f, 0.f, 0.f);
    #pragma unroll
    for (int s = 0; s < SPLIT; s++) {
        const float4 a = *(const float4*)(g_pacc + ((size_t)s * NROWS + rowA) * HDIM + d4 * 4);
        const float4 b = *(const float4*)(g_pacc + ((size_t)s * NROWS + rowB) * HDIM + d4 * 4);
        oA.x = fmaf(wA[s], a.x, oA.x);
        oA.y = fmaf(wA[s], a.y, oA.y);
        oA.z = fmaf(wA[s], a.z, oA.z);
        oA.w = fmaf(wA[s], a.w, oA.w);
        oB.x = fmaf(wB[s], b.x, oB.x);
        oB.y = fmaf(wB[s], b.y, oB.y);
        oB.z = fmaf(wB[s], b.z, oB.z);
        oB.w = fmaf(wB[s], b.w, oB.w);
    }
    const float invA = 1.0f / denA;
    const float invB = 1.0f / denB;
    oA.x *= invA; oA.y *= invA; oA.z *= invA; oA.w *= invA;
    oB.x *= invB; oB.y *= invB; oB.z *= invB; oB.w *= invB;

    const int headA = rowA >> 11, qA = rowA & (LTOK - 1);
    const int headB = rowB >> 11, qB = rowB & (LTOK - 1);
    *(float4*)(g_att + (size_t)qA * DMODEL + headA * HDIM + d4 * 4) = oA;
    *(float4*)(g_att + (size_t)qB * DMODEL + headB * HDIM + d4 * 4) = oB;
}

// ---------------------------------------------------------------------------------
// Fused O-projection + residual + LayerNorm. Tile M=16 x N=256; 256 threads.
// ---------------------------------------------------------------------------------
__global__ void __launch_bounds__(256) gemm_o_ln(
    const float* __restrict__ A, const float* __restrict__ W,
    const float* __restrict__ bias, const float* __restrict__ resid,
    const float* __restrict__ lng, const float* __restrict__ lnb,
    float* __restrict__ out)
{
    __shared__ uint32_t sbuf[5440];
    uint32_t (*As)[20] = (uint32_t (*)[20])sbuf;         // [16][20]
    uint32_t (*Ws)[20] = (uint32_t (*)[20])(sbuf + 320); // [256][20]
    float (*ybuf)[257] = (float (*)[257])sbuf;           // [16][257]

    const int tid  = threadIdx.x;
    const int warp = tid >> 5;
    const int lane = tid & 31;
    const int g  = lane >> 2;
    const int tg = lane & 3;
    const int wc = warp;
    const int m0 = blockIdx.x * 16;

    float acc[4][4];
    #pragma unroll
    for (int nt = 0; nt < 4; nt++)
        #pragma unroll
        for (int j = 0; j < 4; j++) acc[nt][j] = 0.0f;

    for (int k0 = 0; k0 < DMODEL; k0 += 16) {
        if (tid < 64) {
            const int r = tid >> 2, c4 = (tid & 3) << 2;
            *(uint4*)&As[r][c4] = *(const uint4*)(A + (size_t)(m0 + r) * DMODEL + k0 + c4);
        }
        #pragma unroll
        for (int i = tid; i < 1024; i += 256) {
            const int r = i >> 2, c4 = (i & 3) << 2;
            *(uint4*)&Ws[r][c4] = *(const uint4*)(W + (size_t)r * DMODEL + k0 + c4);
        }
        __syncthreads();

        #pragma unroll
        for (int kf = 0; kf < 2; kf++) {
            uint32_t a[4];
            a[0] = As[g    ][kf * 8 + tg    ];
            a[1] = As[g + 8][kf * 8 + tg    ];
            a[2] = As[g    ][kf * 8 + tg + 4];
            a[3] = As[g + 8][kf * 8 + tg + 4];
            #pragma unroll
            for (int nt = 0; nt < 4; nt++) {
                mma_tf32(acc[nt], a, Ws[wc * 32 + nt * 8 + g][kf * 8 + tg],
                                     Ws[wc * 32 + nt * 8 + g][kf * 8 + tg + 4]);
            }
        }
        __syncthreads();
    }

    #pragma unroll
    for (int nt = 0; nt < 4; nt++) {
        const int n = wc * 32 + nt * 8 + 2 * tg;
        float2 bb = *(const float2*)(bias + n);
        float2 r0 = *(const float2*)(resid + (size_t)(m0 + g    ) * DMODEL + n);
        float2 r1 = *(const float2*)(resid + (size_t)(m0 + g + 8) * DMODEL + n);
        ybuf[g    ][n    ] = acc[nt][0] + bb.x + r0.x;
        ybuf[g    ][n + 1] = acc[nt][1] + bb.y + r0.y;
        ybuf[g + 8][n    ] = acc[nt][2] + bb.x + r1.x;
        ybuf[g + 8][n + 1] = acc[nt][3] + bb.y + r1.y;
    }
    __syncthreads();

    #pragma unroll
    for (int it = 0; it < 2; it++) {
        const int row = warp * 2 + it;
        float vals[8];
        float sum = 0.0f;
        #pragma unroll
        for (int j = 0; j < 8; j++) {
            vals[j] = ybuf[row][lane + 32 * j];
            sum += vals[j];
        }
        #pragma unroll
        for (int o = 16; o; o >>= 1) sum += __shfl_xor_sync(0xffffffffu, sum, o);
        const float mu = sum * (1.0f / 256.0f);
        float sq = 0.0f;
        #pragma unroll
        for (int j = 0; j < 8; j++) {
            const float d = vals[j] - mu;
            sq += d * d;
        }
        #pragma unroll
        for (int o = 16; o; o >>= 1) sq += __shfl_xor_sync(0xffffffffu, sq, o);
        const float rstd = rsqrtf(sq * (1.0f / 256.0f) + LN_EPS);
        #pragma unroll
        for (int j = 0; j < 8; j++) {
            const int col = lane + 32 * j;
            out[(size_t)(m0 + row) * DMODEL + col] =
                (vals[j] - mu) * rstd * lng[col] + lnb[col];
        }
    }
}

// ---------------------------------------------------------------------------------
extern "C" void kernel_launch(void* const* d_in, const int* in_sizes, int n_in,
                              void* d_out, int out_size)
{
    const float* x    = (const float*)d_in[0];
    const float* pts  = (const float*)d_in[1];
    const float* Wq   = (const float*)d_in[2];
    const float* bq   = (const float*)d_in[3];
    const float* Wk   = (const float*)d_in[4];
    const float* bk   = (const float*)d_in[5];
    const float* Wv   = (const float*)d_in[6];
    const float* bv   = (const float*)d_in[7];
    const float* Wo   = (const float*)d_in[8];
    const float* bo   = (const float*)d_in[9];
    const float* beta = (const float*)d_in[10];
    const float* kw1  = (const float*)d_in[11];
    const float* kb1  = (const float*)d_in[12];
    const float* kw2  = (const float*)d_in[13];
    const float* kb2  = (const float*)d_in[14];
    const float* lng  = (const float*)d_in[15];
    const float* lnb  = (const float*)d_in[16];
    float* out = (float*)d_out;

    float *Qb, *Ab;
    cudaGetSymbolAddress((void**)&Qb, g_Q);
    cudaGetSymbolAddress((void**)&Ab, g_att);

    setup_geo_tables<<<1, 1>>>(kw1, kb1, kw2, kb2);

    gemm_qkv<<<dim3(DMODEL/64, LTOK/64, 3), 128>>>(x, Wq, bq, Wk, bk, Wv, bv, Qb);

    geo_bias_kernel<<<LTOK / 4, 256>>>(pts, beta);

    attn_kernel<<<NHEADS * 16 * SPLIT, 128>>>();
    merge_kernel<<<NROWS * 8 / 512, 256>>>();

    gemm_o_ln<<<LTOK / 16, 256>>>(Ab, Wo, bo, x, lng, lnb, out);
}

// round 17
// speedup vs baseline: 1.0444x; 1.0188x over previous
#include <cuda_runtime.h>
#include <math.h>
#include <stdint.h>
#include <cuda_fp16.h>

#define LTOK 2048
#define DMODEL 256
#define NHEADS 8
#define HDIM 32
#define SCALE 0.17677669529663687f  /* 32^-0.5 */
#define LOG2E 1.4426950408889634f
#define LN_EPS 1e-5f
#define SPLIT 8
#define KEYS_PER_SPLIT (LTOK / SPLIT)   /* 256 */
#define NROWS (NHEADS * LTOK)           /* 16384 */

// ---------------- scratch (device globals; no allocation allowed) ----------------
__device__ float    g_Q[LTOK * DMODEL];
__device__ uint32_t g_KhU[NHEADS * LTOK * (HDIM / 2)];  // K f16x2, [head][tok][d/2]
__device__ __half   g_Vth[NHEADS * HDIM * LTOK];        // V f16 transposed [head][d][tok]
__device__ float    g_bias[LTOK * LTOK];                // log2e * beta * clip(bias)
__device__ float    g_att[LTOK * DMODEL];
__device__ float    g_pacc[SPLIT * NROWS * HDIM];
__device__ float    g_pm[SPLIT * NROWS];                // log2-domain maxes
__device__ float    g_pl[SPLIT * NROWS];
__device__ float    g_T[32];
__device__ float    g_S[33];
__device__ float    g_C[33];

// ---------------------------------------------------------------------------------
// helpers
// ---------------------------------------------------------------------------------
__device__ __forceinline__ uint32_t pack_f16(float lo, float hi) {
    uint32_t r;
    asm("cvt.rn.f16x2.f32 %0, %1, %2;" : "=r"(r) : "f"(hi), "f"(lo));
    return r;
}

__device__ __forceinline__ void mma_tf32(float c[4], const uint32_t a[4],
                                         uint32_t b0, uint32_t b1) {
    asm volatile(
        "mma.sync.aligned.m16n8k8.row.col.f32.tf32.tf32.f32 "
        "{%0,%1,%2,%3}, {%4,%5,%6,%7}, {%8,%9}, {%0,%1,%2,%3};\n"
        : "+f"(c[0]), "+f"(c[1]), "+f"(c[2]), "+f"(c[3])
        : "r"(a[0]), "r"(a[1]), "r"(a[2]), "r"(a[3]), "r"(b0), "r"(b1));
}

__device__ __forceinline__ void mma_f16(float c[4], const uint32_t a[4],
                                        uint32_t b0, uint32_t b1) {
    asm volatile(
        "mma.sync.aligned.m16n8k16.row.col.f32.f16.f16.f32 "
        "{%0,%1,%2,%3}, {%4,%5,%6,%7}, {%8,%9}, {%0,%1,%2,%3};\n"
        : "+f"(c[0]), "+f"(c[1]), "+f"(c[2]), "+f"(c[3])
        : "r"(a[0]), "r"(a[1]), "r"(a[2]), "r"(a[3]), "r"(b0), "r"(b1));
}

// ---------------------------------------------------------------------------------
// QKV GEMM: tile 64(M) x 64(N), 128 threads, raw-bit tf32 staging.
// mode 0 = Q (f32), 1 = K (f16 packed head-blocked), 2 = V (f16 transposed).
// ---------------------------------------------------------------------------------
__global__ void __launch_bounds__(128) gemm_qkv(
    const float* __restrict__ x,
    const float* __restrict__ Wq, const float* __restrict__ bq,
    const float* __restrict__ Wk, const float* __restrict__ bk,
    const float* __restrict__ Wv, const float* __restrict__ bv,
    float* __restrict__ Qo)
{
    __shared__ uint32_t As[64][20];
    __shared__ uint32_t Ws[64][20];
    const int mode = blockIdx.z;
    const float* W; const float* b;
    if (mode == 0)      { W = Wq; b = bq; }
    else if (mode == 1) { W = Wk; b = bk; }
    else                { W = Wv; b = bv; }

    const int tid  = threadIdx.x;
    const int warp = tid >> 5;
    const int lane = tid & 31;
    const int g  = lane >> 2;
    const int tg = lane & 3;
    const int m0 = blockIdx.y * 64, n0 = blockIdx.x * 64;

    float acc[8][4];
    #pragma unroll
    for (int nt = 0; nt < 8; nt++)
        #pragma unroll
        for (int j = 0; j < 4; j++) acc[nt][j] = 0.0f;

    for (int k0 = 0; k0 < DMODEL; k0 += 16) {
        #pragma unroll
        for (int i = tid; i < 256; i += 128) {
            const int r = i >> 2, c4 = (i & 3) << 2;
            *(uint4*)&As[r][c4] = *(const uint4*)(x + (size_t)(m0 + r) * DMODEL + k0 + c4);
            *(uint4*)&Ws[r][c4] = *(const uint4*)(W + (size_t)(n0 + r) * DMODEL + k0 + c4);
        }
        __syncthreads();

        #pragma unroll
        for (int kf = 0; kf < 2; kf++) {
            uint32_t a[4];
            a[0] = As[warp * 16 + g    ][kf * 8 + tg    ];
            a[1] = As[warp * 16 + g + 8][kf * 8 + tg    ];
            a[2] = As[warp * 16 + g    ][kf * 8 + tg + 4];
            a[3] = As[warp * 16 + g + 8][kf * 8 + tg + 4];
            #pragma unroll
            for (int nt = 0; nt < 8; nt++) {
                mma_tf32(acc[nt], a, Ws[nt * 8 + g][kf * 8 + tg],
                                     Ws[nt * 8 + g][kf * 8 + tg + 4]);
            }
        }
        __syncthreads();
    }

    const int mA = m0 + warp * 16 + g;
    const int mB = mA + 8;
    #pragma unroll
    for (int nt = 0; nt < 8; nt++) {
        const int n = n0 + nt * 8 + 2 * tg;
        float2 bb = *(const float2*)(b + n);
        const float v0 = acc[nt][0] + bb.x, v1 = acc[nt][1] + bb.y;
        const float v2 = acc[nt][2] + bb.x, v3 = acc[nt][3] + bb.y;
        if (mode == 0) {
            *(float2*)(Qo + (size_t)mA * DMODEL + n) = make_float2(v0, v1);
            *(float2*)(Qo + (size_t)mB * DMODEL + n) = make_float2(v2, v3);
        } else {
            const int head = n >> 5, dh = n & 31;
            if (mode == 1) {
                g_KhU[((size_t)head * LTOK + mA) * 16 + (dh >> 1)] = pack_f16(v0, v1);
                g_KhU[((size_t)head * LTOK + mB) * 16 + (dh >> 1)] = pack_f16(v2, v3);
            } else {
                __half* vb = g_Vth + (size_t)head * (HDIM * LTOK);
                vb[(dh    ) * LTOK + mA] = __float2half(v0);
                vb[(dh + 1) * LTOK + mA] = __float2half(v1);
                vb[(dh    ) * LTOK + mB] = __float2half(v2);
                vb[(dh + 1) * LTOK + mB] = __float2half(v3);
            }
        }
    }
}

// ---------------------------------------------------------------------------------
// Setup: bias MLP piecewise-linear tables. 1 thread.
// ---------------------------------------------------------------------------------
__global__ void setup_geo_tables(
    const float* __restrict__ kw1, const float* __restrict__ kb1,
    const float* __restrict__ kw2, const float* __restrict__ kb2)
{
    float t[32], ds[32], dc[32];
    int n = 0;
    float S0 = 0.0f, C0 = kb2[0];
    for (int j = 0; j < 32; j++) {
        const float w1 = kw1[j], b1 = kb1[j], w2 = kw2[j];
        if (b1 > 0.0f) { S0 += w1 * w2; C0 += b1 * w2; }
        if (w1 > 0.0f && !(b1 > 0.0f)) {
            t[n] = -b1 / w1; ds[n] = w1 * w2; dc[n] = b1 * w2; n++;
        } else if (w1 < 0.0f && b1 > 0.0f) {
            t[n] = -b1 / w1; ds[n] = -w1 * w2; dc[n] = -b1 * w2; n++;
        }
    }
    for (int i = 1; i < n; i++) {
        float tv = t[i], sv = ds[i], cv = dc[i];
        int j = i - 1;
        while (j >= 0 && t[j] > tv) { t[j+1]=t[j]; ds[j+1]=ds[j]; dc[j+1]=dc[j]; j--; }
        t[j+1] = tv; ds[j+1] = sv; dc[j+1] = cv;
    }
    g_S[0] = S0; g_C[0] = C0;
    for (int i = 0; i < 32; i++) {
        if (i < n) {
            g_T[i] = t[i];
            g_S[i+1] = g_S[i] + ds[i];
            g_C[i+1] = g_C[i] + dc[i];
        } else {
            g_T[i] = INFINITY;
            g_S[i+1] = g_S[i];
            g_C[i+1] = g_C[i];
        }
    }
}

// ---------------------------------------------------------------------------------
// Geometric bias via table lookup. Output pre-scaled by beta*LOG2E (log2 domain).
// ---------------------------------------------------------------------------------
__global__ void __launch_bounds__(256) geo_bias_kernel(
    const float* __restrict__ pts, const float* __restrict__ beta)
{
    __shared__ float sp[LTOK * 3];
    __shared__ float sT[32], sS[33], sC[33];
    const int tid = threadIdx.x;
    for (int i = tid; i < LTOK * 3; i += 256) sp[i] = pts[i];
    if (tid < 32) sT[tid] = g_T[tid];
    if (tid < 33) { sS[tid] = g_S[tid]; sC[tid] = g_C[tid]; }
    __syncthreads();

    const float bet = beta[0] * LOG2E;
    const int qbase = blockIdx.x * 4;

    #pragma unroll
    for (int qi = 0; qi < 4; qi++) {
        const int q = qbase + qi;
        const float qx = sp[q*3+0], qy = sp[q*3+1], qz = sp[q*3+2];
        for (int k = tid; k < LTOK; k += 256) {
            const float dx = qx - sp[k*3+0];
            const float dy = qy - sp[k*3+1];
            const float dz = qz - sp[k*3+2];
            const float d = sqrtf(dx*dx + dy*dy + dz*dz);
            int i = 0;
            #pragma unroll
            for (int s = 16; s; s >>= 1) if (sT[i + s - 1] < d) i += s;
            const float b = fmaf(sS[i], d, sC[i]);
            g_bias[q * LTOK + k] = bet * fminf(fmaxf(b, -10.0f), 0.0f);
        }
    }
}

// ---------------------------------------------------------------------------------
// Flash attention, f16 mma both phases, register-direct P, SPLIT-K x8,
// log2-domain softmax (bare exp2f). HEAD IS THE FASTEST blockIdx digit so the
// 8 CTAs sharing a (qtile,split) bias region are co-resident -> 7/8 of bias
// reads become L2 hot-line hits (bias is head-independent).
// CTA: 128 threads / 4 warps / 128 queries; 256 keys per CTA. Grid = 1024.
// ---------------------------------------------------------------------------------
__global__ void __launch_bounds__(128) attn_kernel()
{
    __shared__ uint32_t Kt[64][20];   // K tile [key][d-pair f16x2]
    __shared__ __half   Vt[32][72];   // V tile transposed [d][key], f16

    const int tid  = threadIdx.x;
    const int warp = tid >> 5;
    const int lane = tid & 31;
    const int g  = lane >> 2;
    const int tg = lane & 3;

    const int head  = blockIdx.x & 7;          // fastest: bias-sharing CTAs adjacent
    const int split = (blockIdx.x >> 3) & 7;
    const int qtile = blockIdx.x >> 6;
    const int qw = qtile * 128 + warp * 32;
    const int kbeg = split * KEYS_PER_SPLIT;

    const uint32_t* Ksrc = g_KhU + (size_t)head * LTOK * 16;
    const __half*   Vsrc = g_Vth + (size_t)head * (HDIM * LTOK);

    // Q fragments (f16, pre-scaled by SCALE*LOG2E)
    const float QS = SCALE * LOG2E;
    uint32_t qfA[2][4], qfB[2][4];
    {
        const float* Qb = g_Q + (size_t)qw * DMODEL + head * HDIM;
        #pragma unroll
        for (int ks = 0; ks < 2; ks++) {
            #pragma unroll
            for (int half = 0; half < 2; half++) {
                const int dof = ks * 16 + half * 8 + 2 * tg;
                float2 q0 = *(const float2*)(Qb + (g     ) * DMODEL + dof);
                float2 q1 = *(const float2*)(Qb + (g +  8) * DMODEL + dof);
                float2 q2 = *(const float2*)(Qb + (g + 16) * DMODEL + dof);
                float2 q3 = *(const float2*)(Qb + (g + 24) * DMODEL + dof);
                qfA[ks][half * 2    ] = pack_f16(QS * q0.x, QS * q0.y);
                qfA[ks][half * 2 + 1] = pack_f16(QS * q1.x, QS * q1.y);
                qfB[ks][half * 2    ] = pack_f16(QS * q2.x, QS * q2.y);
                qfB[ks][half * 2 + 1] = pack_f16(QS * q3.x, QS * q3.y);
            }
        }
    }

    float oA[4][4], oB[4][4];
    #pragma unroll
    for (int nt = 0; nt < 4; nt++)
        #pragma unroll
        for (int j = 0; j < 4; j++) { oA[nt][j] = 0.0f; oB[nt][j] = 0.0f; }
    float mA0 = -INFINITY, mA1 = -INFINITY, mB0 = -INFINITY, mB1 = -INFINITY;
    float lA0 = 0.0f, lA1 = 0.0f, lB0 = 0.0f, lB1 = 0.0f;

    const float* b0p = g_bias + (size_t)(qw + g) * LTOK + 2 * tg;
    const float* b1p = b0p +  8 * LTOK;
    const float* b2p = b0p + 16 * LTOK;
    const float* b3p = b0p + 24 * LTOK;

    #pragma unroll 1
    for (int t0 = kbeg; t0 < kbeg + KEYS_PER_SPLIT; t0 += 64) {
        // ---- stage K/V: pure vector copies (pre-converted f16 layouts) ----
        #pragma unroll
        for (int i = tid; i < 512; i += 128) {
            const int r = i >> 3, seg = i & 7;
            *(uint2*)&Kt[r][seg * 2] =
                *(const uint2*)(Ksrc + (size_t)(t0 + r) * 16 + seg * 2);
        }
        #pragma unroll
        for (int i = tid; i < 256; i += 128) {
            const int d = i >> 3, seg = i & 7;
            *(uint4*)&Vt[d][seg * 8] =
                *(const uint4*)(Vsrc + (size_t)d * LTOK + t0 + seg * 8);
        }
        __syncthreads();

        // ---- scores (f16 mma) with bias pipelined one nt ahead ----
        float sA[8][4], sB[8][4];
        float2 nb0 = *(const float2*)(b0p + t0);
        float2 nb1 = *(const float2*)(b1p + t0);
        float2 nb2 = *(const float2*)(b2p + t0);
        float2 nb3 = *(const float2*)(b3p + t0);
        #pragma unroll
        for (int nt = 0; nt < 8; nt++) {
            const float2 bb0 = nb0, bb1 = nb1, bb2 = nb2, bb3 = nb3;
            if (nt < 7) {
                nb0 = *(const float2*)(b0p + t0 + (nt + 1) * 8);
                nb1 = *(const float2*)(b1p + t0 + (nt + 1) * 8);
                nb2 = *(const float2*)(b2p + t0 + (nt + 1) * 8);
                nb3 = *(const float2*)(b3p + t0 + (nt + 1) * 8);
            }
            sA[nt][0] = bb0.x; sA[nt][1] = bb0.y;
            sA[nt][2] = bb1.x; sA[nt][3] = bb1.y;
            sB[nt][0] = bb2.x; sB[nt][1] = bb2.y;
            sB[nt][2] = bb3.x; sB[nt][3] = bb3.y;
            #pragma unroll
            for (int ks = 0; ks < 2; ks++) {
                const uint32_t kb0 = Kt[nt * 8 + g][ks * 8 + tg];
                const uint32_t kb1 = Kt[nt * 8 + g][ks * 8 + tg + 4];
                mma_f16(sA[nt], qfA[ks], kb0, kb1);
                mma_f16(sB[nt], qfB[ks], kb0, kb1);
            }
        }

        // ---- online softmax maxes (log2 domain) ----
        float x0 = -INFINITY, x1 = -INFINITY, x2 = -INFINITY, x3 = -INFINITY;
        #pragma unroll
        for (int nt = 0; nt < 8; nt++) {
            x0 = fmaxf(x0, fmaxf(sA[nt][0], sA[nt][1]));
            x1 = fmaxf(x1, fmaxf(sA[nt][2], sA[nt][3]));
            x2 = fmaxf(x2, fmaxf(sB[nt][0], sB[nt][1]));
            x3 = fmaxf(x3, fmaxf(sB[nt][2], sB[nt][3]));
        }
        x0 = fmaxf(x0, __shfl_xor_sync(0xffffffffu, x0, 1));
        x0 = fmaxf(x0, __shfl_xor_sync(0xffffffffu, x0, 2));
        x1 = fmaxf(x1, __shfl_xor_sync(0xffffffffu, x1, 1));
        x1 = fmaxf(x1, __shfl_xor_sync(0xffffffffu, x1, 2));
        x2 = fmaxf(x2, __shfl_xor_sync(0xffffffffu, x2, 1));
        x2 = fmaxf(x2, __shfl_xor_sync(0xffffffffu, x2, 2));
        x3 = fmaxf(x3, __shfl_xor_sync(0xffffffffu, x3, 1));
        x3 = fmaxf(x3, __shfl_xor_sync(0xffffffffu, x3, 2));

        const float nA0 = fmaxf(mA0, x0), nA1 = fmaxf(mA1, x1);
        const float nB0 = fmaxf(mB0, x2), nB1 = fmaxf(mB1, x3);
        const float cA0 = exp2f(mA0 - nA0), cA1 = exp2f(mA1 - nA1);
        const float cB0 = exp2f(mB0 - nB0), cB1 = exp2f(mB1 - nB1);
        mA0 = nA0; mA1 = nA1; mB0 = nB0; mB1 = nB1;

        #pragma unroll
        for (int nt = 0; nt < 4; nt++) {
            oA[nt][0] *= cA0; oA[nt][1] *= cA0;
            oA[nt][2] *= cA1; oA[nt][3] *= cA1;
            oB[nt][0] *= cB0; oB[nt][1] *= cB0;
            oB[nt][2] *= cB1; oB[nt][3] *= cB1;
        }
        lA0 *= cA0; lA1 *= cA1; lB0 *= cB0; lB1 *= cB1;

        // ---- FUSED exp2 -> f16 pack -> PV mma, per kc chunk ----
        #pragma unroll
        for (int kc = 0; kc < 4; kc++) {
            const int n0i = 2 * kc, n1i = 2 * kc + 1;
            uint32_t aA[4], aB[4];
            {
                const float pA0 = exp2f(sA[n0i][0] - nA0);
                const float pA1 = exp2f(sA[n0i][1] - nA0);
                const float pA2 = exp2f(sA[n0i][2] - nA1);
                const float pA3 = exp2f(sA[n0i][3] - nA1);
                const float pA4 = exp2f(sA[n1i][0] - nA0);
                const float pA5 = exp2f(sA[n1i][1] - nA0);
                const float pA6 = exp2f(sA[n1i][2] - nA1);
                const float pA7 = exp2f(sA[n1i][3] - nA1);
                lA0 += pA0 + pA1 + pA4 + pA5;
                lA1 += pA2 + pA3 + pA6 + pA7;
                aA[0] = pack_f16(pA0, pA1);
                aA[1] = pack_f16(pA2, pA3);
                aA[2] = pack_f16(pA4, pA5);
                aA[3] = pack_f16(pA6, pA7);
            }
            {
                const float pB0 = exp2f(sB[n0i][0] - nB0);
                const float pB1 = exp2f(sB[n0i][1] - nB0);
                const float pB2 = exp2f(sB[n0i][2] - nB1);
                const float pB3 = exp2f(sB[n0i][3] - nB1);
                const float pB4 = exp2f(sB[n1i][0] - nB0);
                const float pB5 = exp2f(sB[n1i][1] - nB0);
                const float pB6 = exp2f(sB[n1i][2] - nB1);
                const float pB7 = exp2f(sB[n1i][3] - nB1);
                lB0 += pB0 + pB1 + pB4 + pB5;
                lB1 += pB2 + pB3 + pB6 + pB7;
                aB[0] = pack_f16(pB0, pB1);
                aB[1] = pack_f16(pB2, pB3);
                aB[2] = pack_f16(pB4, pB5);
                aB[3] = pack_f16(pB6, pB7);
            }
            #pragma unroll
            for (int nt = 0; nt < 4; nt++) {
                const uint32_t vb0 = *(const uint32_t*)&Vt[nt * 8 + g][kc * 16 + 2 * tg];
                const uint32_t vb1 = *(const uint32_t*)&Vt[nt * 8 + g][kc * 16 + 2 * tg + 8];
                mma_f16(oA[nt], aA, vb0, vb1);
                mma_f16(oB[nt], aB, vb0, vb1);
            }
        }
        __syncthreads();
    }

    // ---- final quad reduction of l ----
    lA0 += __shfl_xor_sync(0xffffffffu, lA0, 1);
    lA0 += __shfl_xor_sync(0xffffffffu, lA0, 2);
    lA1 += __shfl_xor_sync(0xffffffffu, lA1, 1);
    lA1 += __shfl_xor_sync(0xffffffffu, lA1, 2);
    lB0 += __shfl_xor_sync(0xffffffffu, lB0, 1);
    lB0 += __shfl_xor_sync(0xffffffffu, lB0, 2);
    lB1 += __shfl_xor_sync(0xffffffffu, lB1, 1);
    lB1 += __shfl_xor_sync(0xffffffffu, lB1, 2);

    // ---- store unnormalized partials + (m, l) ----
    const int rA0 = head * LTOK + qw + g;
    const int rA1 = rA0 + 8;
    const int rB0 = rA0 + 16;
    const int rB1 = rA0 + 24;
    float* pA0 = g_pacc + ((size_t)split * NROWS + rA0) * HDIM + 2 * tg;
    float* pA1 = g_pacc + ((size_t)split * NROWS + rA1) * HDIM + 2 * tg;
    float* pB0 = g_pacc + ((size_t)split * NROWS + rB0) * HDIM + 2 * tg;
    float* pB1 = g_pacc + ((size_t)split * NROWS + rB1) * HDIM + 2 * tg;
    #pragma unroll
    for (int nt = 0; nt < 4; nt++) {
        *(float2*)(pA0 + nt * 8) = make_float2(oA[nt][0], oA[nt][1]);
        *(float2*)(pA1 + nt * 8) = make_float2(oA[nt][2], oA[nt][3]);
        *(float2*)(pB0 + nt * 8) = make_float2(oB[nt][0], oB[nt][1]);
        *(float2*)(pB1 + nt * 8) = make_float2(oB[nt][2], oB[nt][3]);
    }
    if (tg == 0) {
        g_pm[split * NROWS + rA0] = mA0;  g_pl[split * NROWS + rA0] = lA0;
        g_pm[split * NROWS + rA1] = mA1;  g_pl[split * NROWS + rA1] = lA1;
        g_pm[split * NROWS + rB0] = mB0;  g_pl[split * NROWS + rB0] = lB0;
        g_pm[split * NROWS + rB1] = mB1;  g_pl[split * NROWS + rB1] = lB1;
    }
}

// ---------------------------------------------------------------------------------
// Merge split-K partials (round-13 proven version; m's log2-domain -> exp2f).
// ---------------------------------------------------------------------------------
__global__ void __launch_bounds__(256) merge_kernel()
{
    const int idx = blockIdx.x * 256 + threadIdx.x;
    const int row = idx >> 3, d4 = idx & 7;

    float mv[SPLIT];
    float mstar = -INFINITY;
    #pragma unroll
    for (int s = 0; s < SPLIT; s++) {
        mv[s] = g_pm[s * NROWS + row];
        mstar = fmaxf(mstar, mv[s]);
    }
    float denom = 0.0f;
    float4 o = make_float4(0.f, 0.f, 0.f, 0.f);
    #pragma unroll
    for (int s = 0; s < SPLIT; s++) {
        const float w = exp2f(mv[s] - mstar);
        denom = fmaf(w, g_pl[s * NROWS + row], denom);
        const float4 a = *(const float4*)(g_pacc + ((size_t)s * NROWS + row) * HDIM + d4 * 4);
        o.x = fmaf(w, a.x, o.x);
        o.y = fmaf(w, a.y, o.y);
        o.z = fmaf(w, a.z, o.z);
        o.w = fmaf(w, a.w, o.w);
    }
    const float inv = 1.0f / denom;
    o.x *= inv; o.y *= inv; o.z *= inv; o.w *= inv;

    const int head = row >> 11, q = row & (LTOK - 1);
    *(float4*)(g_att + (size_t)q * DMODEL + head * HDIM + d4 * 4) = o;
}

// ---------------------------------------------------------------------------------
// Fused O-projection + residual + LayerNorm. Tile M=16 x N=256; 256 threads.
// ---------------------------------------------------------------------------------
__global__ void __launch_bounds__(256) gemm_o_ln(
    const float* __restrict__ A, const float* __restrict__ W,
    const float* __restrict__ bias, const float* __restrict__ resid,
    const float* __restrict__ lng, const float* __restrict__ lnb,
    float* __restrict__ out)
{
    __shared__ uint32_t sbuf[5440];
    uint32_t (*As)[20] = (uint32_t (*)[20])sbuf;         // [16][20]
    uint32_t (*Ws)[20] = (uint32_t (*)[20])(sbuf + 320); // [256][20]
    float (*ybuf)[257] = (float (*)[257])sbuf;           // [16][257]

    const int tid  = threadIdx.x;
    const int warp = tid >> 5;
    const int lane = tid & 31;
    const int g  = lane >> 2;
    const int tg = lane & 3;
    const int wc = warp;
    const int m0 = blockIdx.x * 16;

    float acc[4][4];
    #pragma unroll
    for (int nt = 0; nt < 4; nt++)
        #pragma unroll
        for (int j = 0; j < 4; j++) acc[nt][j] = 0.0f;

    for (int k0 = 0; k0 < DMODEL; k0 += 16) {
        if (tid < 64) {
            const int r = tid >> 2, c4 = (tid & 3) << 2;
            *(uint4*)&As[r][c4] = *(const uint4*)(A + (size_t)(m0 + r) * DMODEL + k0 + c4);
        }
        #pragma unroll
        for (int i = tid; i < 1024; i += 256) {
            const int r = i >> 2, c4 = (i & 3) << 2;
            *(uint4*)&Ws[r][c4] = *(const uint4*)(W + (size_t)r * DMODEL + k0 + c4);
        }
        __syncthreads();

        #pragma unroll
        for (int kf = 0; kf < 2; kf++) {
            uint32_t a[4];
            a[0] = As[g    ][kf * 8 + tg    ];
            a[1] = As[g + 8][kf * 8 + tg    ];
            a[2] = As[g    ][kf * 8 + tg + 4];
            a[3] = As[g + 8][kf * 8 + tg + 4];
            #pragma unroll
            for (int nt = 0; nt < 4; nt++) {
                mma_tf32(acc[nt], a, Ws[wc * 32 + nt * 8 + g][kf * 8 + tg],
                                     Ws[wc * 32 + nt * 8 + g][kf * 8 + tg + 4]);
            }
        }
        __syncthreads();
    }

    #pragma unroll
    for (int nt = 0; nt < 4; nt++) {
        const int n = wc * 32 + nt * 8 + 2 * tg;
        float2 bb = *(const float2*)(bias + n);
        float2 r0 = *(const float2*)(resid + (size_t)(m0 + g    ) * DMODEL + n);
        float2 r1 = *(const float2*)(resid + (size_t)(m0 + g + 8) * DMODEL + n);
        ybuf[g    ][n    ] = acc[nt][0] + bb.x + r0.x;
        ybuf[g    ][n + 1] = acc[nt][1] + bb.y + r0.y;
        ybuf[g + 8][n    ] = acc[nt][2] + bb.x + r1.x;
        ybuf[g + 8][n + 1] = acc[nt][3] + bb.y + r1.y;
    }
    __syncthreads();

    #pragma unroll
    for (int it = 0; it < 2; it++) {
        const int row = warp * 2 + it;
        float vals[8];
        float sum = 0.0f;
        #pragma unroll
        for (int j = 0; j < 8; j++) {
            vals[j] = ybuf[row][lane + 32 * j];
            sum += vals[j];
        }
        #pragma unroll
        for (int o = 16; o; o >>= 1) sum += __shfl_xor_sync(0xffffffffu, sum, o);
        const float mu = sum * (1.0f / 256.0f);
        float sq = 0.0f;
        #pragma unroll
        for (int j = 0; j < 8; j++) {
            const float d = vals[j] - mu;
            sq += d * d;
        }
        #pragma unroll
        for (int o = 16; o; o >>= 1) sq += __shfl_xor_sync(0xffffffffu, sq, o);
        const float rstd = rsqrtf(sq * (1.0f / 256.0f) + LN_EPS);
        #pragma unroll
        for (int j = 0; j < 8; j++) {
            const int col = lane + 32 * j;
            out[(size_t)(m0 + row) * DMODEL + col] =
                (vals[j] - mu) * rstd * lng[col] + lnb[col];
        }
    }
}

// ---------------------------------------------------------------------------------
extern "C" void kernel_launch(void* const* d_in, const int* in_sizes, int n_in,
                              void* d_out, int out_size)
{
    const float* x    = (const float*)d_in[0];
    const float* pts  = (const float*)d_in[1];
    const float* Wq   = (const float*)d_in[2];
    const float* bq   = (const float*)d_in[3];
    const float* Wk   = (const float*)d_in[4];
    const float* bk   = (const float*)d_in[5];
    const float* Wv   = (const float*)d_in[6];
    const float* bv   = (const float*)d_in[7];
    const float* Wo   = (const float*)d_in[8];
    const float* bo   = (const float*)d_in[9];
    const float* beta = (const float*)d_in[10];
    const float* kw1  = (const float*)d_in[11];
    const float* kb1  = (const float*)d_in[12];
    const float* kw2  = (const float*)d_in[13];
    const float* kb2  = (const float*)d_in[14];
    const float* lng  = (const float*)d_in[15];
    const float* lnb  = (const float*)d_in[16];
    float* out = (float*)d_out;

    float *Qb, *Ab;
    cudaGetSymbolAddress((void**)&Qb, g_Q);
    cudaGetSymbolAddress((void**)&Ab, g_att);

    setup_geo_tables<<<1, 1>>>(kw1, kb1, kw2, kb2);

    gemm_qkv<<<dim3(DMODEL/64, LTOK/64, 3), 128>>>(x, Wq, bq, Wk, bk, Wv, bv, Qb);

    geo_bias_kernel<<<LTOK / 4, 256>>>(pts, beta);

    attn_kernel<<<NHEADS * 16 * SPLIT, 128>>>();
    merge_kernel<<<NROWS * 8 / 256, 256>>>();

    gemm_o_ln<<<LTOK / 16, 256>>>(Ab, Wo, bo, x, lng, lnb, out);
}